// round 15
// baseline (speedup 1.0000x reference)
#include <cuda_runtime.h>
#include <cuda_fp16.h>
#include <cstdint>

#define M_ROWS   16384
#define F_DIM    1024
#define L_LAYERS 5
#define NPIPE    4
#define M_PIECE  (M_ROWS / NPIPE)   // 4096

#define BM 128
#define BN 128
#define BK 32
#define NCHUNK (F_DIM / BK)   // 32
#define THREADS 512
#define STAGES 4

#define ROW_BYTES   80
#define TILE_BYTES  (128 * ROW_BYTES)       // 10240
#define A_OFF       0u
#define BH_OFF      (1u * TILE_BYTES)
#define BL_OFF      (2u * TILE_BYTES)
#define STAGE_BYTES (3u * TILE_BYTES)       // 30720
#define SMEM_TOTAL  (STAGES * STAGE_BYTES)  // 122880

// ---------------- scratch ----------------
__device__ __half g_Bh[(size_t)L_LAYERS * F_DIM * F_DIM];  // 10 MB
__device__ __half g_Bl[(size_t)L_LAYERS * F_DIM * F_DIM];  // 10 MB
__device__ __half g_A [(size_t)M_ROWS * F_DIM];            // 32 MB  h (fp16): A AND residual
__device__ float g_bufA[(size_t)M_ROWS * F_DIM];           // 64 MB  ypre

// ---------------- helpers ----------------
__device__ __forceinline__ uint32_t smem_u32(const void* p) {
    uint32_t a;
    asm("{ .reg .u64 t; cvta.to.shared.u64 t, %1; cvt.u32.u64 %0, t; }" : "=r"(a) : "l"(p));
    return a;
}
__device__ __forceinline__ void cp_async16(uint32_t dst, const void* src) {
    asm volatile("cp.async.cg.shared.global [%0], [%1], 16;" :: "r"(dst), "l"(src));
}
#define CP_COMMIT()  asm volatile("cp.async.commit_group;")
#define CP_WAIT(n)   asm volatile("cp.async.wait_group %0;" :: "n"(n))

#define LDSM_X4(r, addr) \
    asm volatile("ldmatrix.sync.aligned.m8n8.x4.shared.b16 {%0,%1,%2,%3}, [%4];" \
        : "=r"((r)[0]), "=r"((r)[1]), "=r"((r)[2]), "=r"((r)[3]) : "r"(addr))

__device__ __forceinline__ void mma_f32acc(float* d, const uint32_t* a,
                                           uint32_t b0, uint32_t b1) {
    asm volatile(
        "mma.sync.aligned.m16n8k16.row.col.f32.f16.f16.f32 "
        "{%0,%1,%2,%3}, {%4,%5,%6,%7}, {%8,%9}, {%0,%1,%2,%3};"
        : "+f"(d[0]), "+f"(d[1]), "+f"(d[2]), "+f"(d[3])
        : "r"(a[0]), "r"(a[1]), "r"(a[2]), "r"(a[3]), "r"(b0), "r"(b1));
}
__device__ __forceinline__ void mma_f16acc(uint32_t* d, const uint32_t* a,
                                           uint32_t b0, uint32_t b1) {
    asm volatile(
        "mma.sync.aligned.m16n8k16.row.col.f16.f16.f16.f16 "
        "{%0,%1}, {%2,%3,%4,%5}, {%6,%7}, {%0,%1};"
        : "+r"(d[0]), "+r"(d[1])
        : "r"(a[0]), "r"(a[1]), "r"(a[2]), "r"(a[3]), "r"(b0), "r"(b1));
}

// ---------------- prep: B{h,l}[l][n][k] = split_fp16(W[l][k][n] * adj[k][n]) ----------------
// l0 = first layer handled by this launch (blockIdx.z offsets from it)
__global__ void prep_kernel(const float* __restrict__ W, const float* __restrict__ adj,
                            int l0) {
    __shared__ float tile[32][33];
    const int l = blockIdx.z + l0;
    const int kb = blockIdx.x * 32;
    const int nb = blockIdx.y * 32;
    #pragma unroll
    for (int i = 0; i < 4; i++) {
        int k = kb + threadIdx.y + i * 8;
        int n = nb + threadIdx.x;
        tile[threadIdx.y + i * 8][threadIdx.x] =
            W[((size_t)l * F_DIM + k) * F_DIM + n] * adj[(size_t)k * F_DIM + n];
    }
    __syncthreads();
    #pragma unroll
    for (int i = 0; i < 4; i++) {
        int n = nb + threadIdx.y + i * 8;
        int k = kb + threadIdx.x;
        float v = tile[threadIdx.x][threadIdx.y + i * 8];
        __half h = __float2half(v);
        float rem = v - __half2float(h);
        size_t o = ((size_t)l * F_DIM + n) * F_DIM + k;
        g_Bh[o] = h;
        g_Bl[o] = __float2half(rem);
    }
}

// ---------------- x -> fp16 (per-piece) ----------------
__global__ void tohalf_kernel(const float* __restrict__ X, size_t off4) {
    size_t idx = off4 + (size_t)blockIdx.x * blockDim.x + threadIdx.x;
    float4 v = ((const float4*)X)[idx];
    __half2 p0{__float2half(v.x), __float2half(v.y)};
    __half2 p1{__float2half(v.z), __float2half(v.w)};
    uint2 u;
    u.x = *(uint32_t*)&p0; u.y = *(uint32_t*)&p1;
    ((uint2*)g_A)[idx] = u;
}

// ---------------- GEMM: ypre = relu(A @ (Bh+Bl) + bias) + A   (A fp16; row-local) ----
__global__ void __launch_bounds__(THREADS, 1)
gemm_mma_kernel(const __half* __restrict__ A,
                const __half* __restrict__ Bh, const __half* __restrict__ Bl,
                const float* __restrict__ bias, float* __restrict__ Y)
{
    extern __shared__ char smem[];
    const uint32_t sb = smem_u32(smem);
    const int tid = threadIdx.x;
    const int wid = tid >> 5;
    const int lid = tid & 31;
    const int warpM = wid & 3;     // 4 warps in M, tile 32 rows
    const int warpN = wid >> 2;    // 4 warps in N, tile 32 cols
    const int blockRow = blockIdx.y * BM;
    const int blockCol = blockIdx.x * BN;

    const char* gA  = (const char*)(A  + (size_t)blockRow * F_DIM);
    const char* gBh = (const char*)(Bh + (size_t)blockCol * F_DIM);
    const char* gBl = (const char*)(Bl + (size_t)blockCol * F_DIM);

    auto load_stage = [&](int c, int s) {
        const int k0b = c * BK * 2;
        const uint32_t base = sb + (uint32_t)s * STAGE_BYTES;
        const int r = tid >> 2;
        const int c16 = tid & 3;
        const uint32_t soff = (uint32_t)(r * ROW_BYTES + c16 * 16);
        const size_t goff = (size_t)r * (F_DIM * 2) + k0b + c16 * 16;
        cp_async16(base + A_OFF  + soff, gA  + goff);
        cp_async16(base + BH_OFF + soff, gBh + goff);
        cp_async16(base + BL_OFF + soff, gBl + goff);
    };

    float    acc [2][4][4];
    uint32_t acch[2][4][2];
    #pragma unroll
    for (int mt = 0; mt < 2; mt++)
        #pragma unroll
        for (int nt = 0; nt < 4; nt++) {
            #pragma unroll
            for (int i = 0; i < 4; i++) acc[mt][nt][i] = 0.f;
            acch[mt][nt][0] = 0u; acch[mt][nt][1] = 0u;
        }

    load_stage(0, 0); CP_COMMIT();
    load_stage(1, 1); CP_COMMIT();
    load_stage(2, 2); CP_COMMIT();

    const uint32_t aRowOff = (uint32_t)((warpM * 32 + (lid & 15)) * ROW_BYTES + ((lid >> 4) << 4));
    const uint32_t bRowOff = (uint32_t)((warpN * 32 + (lid & 15)) * ROW_BYTES + ((lid >> 4) << 4));

    for (int c = 0; c < NCHUNK; ++c) {
        CP_WAIT(2);
        __syncthreads();
        if (c + 3 < NCHUNK) load_stage(c + 3, (c + 3) & 3);
        CP_COMMIT();

        const uint32_t stage = sb + (uint32_t)(c & 3) * STAGE_BYTES;
        #pragma unroll
        for (int kh = 0; kh < 2; kh++) {
            const uint32_t kb = (uint32_t)(kh * 32);
            uint32_t a[2][4], bh[2][4], bl[2][4];
            #pragma unroll
            for (int mt = 0; mt < 2; mt++)
                LDSM_X4(a[mt], stage + A_OFF + aRowOff + (uint32_t)(mt * 16 * ROW_BYTES) + kb);
            #pragma unroll
            for (int g = 0; g < 2; g++) {
                LDSM_X4(bh[g], stage + BH_OFF + bRowOff + (uint32_t)(g * 16 * ROW_BYTES) + kb);
                LDSM_X4(bl[g], stage + BL_OFF + bRowOff + (uint32_t)(g * 16 * ROW_BYTES) + kb);
            }
            #pragma unroll
            for (int mt = 0; mt < 2; mt++)
                #pragma unroll
                for (int nt = 0; nt < 4; nt++) {
                    const int g = nt >> 1, h = nt & 1;
                    mma_f32acc(acc[mt][nt], a[mt], bh[g][h], bh[g][h + 2]);
                }
            #pragma unroll
            for (int mt = 0; mt < 2; mt++)
                #pragma unroll
                for (int nt = 0; nt < 4; nt++) {
                    const int g = nt >> 1, h = nt & 1;
                    mma_f16acc(acch[mt][nt], a[mt], bl[g][h], bl[g][h + 2]);
                }
        }
    }

    // ---- epilogue: merge lo acc, bias + relu + residual (fp16 residual from A) ----
    const int lane4 = lid >> 2;
    const int lanec = (lid & 3) * 2;
    float2 bv[4];
    #pragma unroll
    for (int nt = 0; nt < 4; nt++)
        bv[nt] = *(const float2*)(bias + blockCol + warpN * 32 + nt * 8 + lanec);

    #pragma unroll
    for (int mt = 0; mt < 2; mt++) {
        const int r0 = blockRow + warpM * 32 + mt * 16 + lane4;
        const int r1 = r0 + 8;
        #pragma unroll
        for (int nt = 0; nt < 4; nt++) {
            const int col = blockCol + warpN * 32 + nt * 8 + lanec;
            const size_t o0 = (size_t)r0 * F_DIM + col;
            const size_t o1 = (size_t)r1 * F_DIM + col;
            float2 h0 = __half22float2(*(const __half2*)(A + o0));
            float2 h1 = __half22float2(*(const __half2*)(A + o1));
            float* a4 = acc[mt][nt];
            __half2 c0 = *(__half2*)&acch[mt][nt][0];
            __half2 c1 = *(__half2*)&acch[mt][nt][1];
            float s0 = a4[0] + __low2float(c0);
            float s1 = a4[1] + __high2float(c0);
            float s2 = a4[2] + __low2float(c1);
            float s3 = a4[3] + __high2float(c1);
            float2 y0, y1;
            y0.x = fmaxf(s0 + bv[nt].x, 0.f) + h0.x;
            y0.y = fmaxf(s1 + bv[nt].y, 0.f) + h0.y;
            y1.x = fmaxf(s2 + bv[nt].x, 0.f) + h1.x;
            y1.y = fmaxf(s3 + bv[nt].y, 0.f) + h1.y;
            *(float2*)(Y + o0) = y0;
            *(float2*)(Y + o1) = y1;
        }
    }
}

// ---------------- LayerNorm: pointer-parameterized ----------------
__global__ void ln_kernel(const float* __restrict__ Yin, float* __restrict__ OutF32,
                          __half* __restrict__ OutH, int last) {
    const int row = blockIdx.x;
    const size_t base4 = (size_t)row * (F_DIM / 4);
    float4 v = ((const float4*)Yin)[base4 + threadIdx.x];
    float s  = v.x + v.y + v.z + v.w;
    float ss = v.x * v.x + v.y * v.y + v.z * v.z + v.w * v.w;
    #pragma unroll
    for (int o = 16; o > 0; o >>= 1) {
        s  += __shfl_down_sync(0xffffffffu, s,  o);
        ss += __shfl_down_sync(0xffffffffu, ss, o);
    }
    __shared__ float sh_s[8], sh_ss[8];
    const int warp = threadIdx.x >> 5, lane = threadIdx.x & 31;
    if (lane == 0) { sh_s[warp] = s; sh_ss[warp] = ss; }
    __syncthreads();
    float st = 0.f, sst = 0.f;
    #pragma unroll
    for (int w = 0; w < 8; w++) { st += sh_s[w]; sst += sh_ss[w]; }
    const float inv = 1.0f / (float)F_DIM;
    const float mu  = st * inv;
    const float var = sst * inv - mu * mu;
    const float r   = rsqrtf(var + 1e-5f);
    v.x = (v.x - mu) * r; v.y = (v.y - mu) * r;
    v.z = (v.z - mu) * r; v.w = (v.w - mu) * r;
    if (last) {
        ((float4*)OutF32)[base4 + threadIdx.x] = v;
    } else {
        __half2 p0{__float2half(v.x), __float2half(v.y)};
        __half2 p1{__float2half(v.z), __float2half(v.w)};
        uint2 u;
        u.x = *(uint32_t*)&p0; u.y = *(uint32_t*)&p1;
        ((uint2*)OutH)[base4 + threadIdx.x] = u;
    }
}

// ---------------- launch: 4-way pipelines; layers-1..4 prep overlapped on st[1] ----------------
extern "C" void kernel_launch(void* const* d_in, const int* in_sizes, int n_in,
                              void* d_out, int out_size) {
    const float* x    = (const float*)d_in[0];   // (16384, 1024)
    const float* adj  = (const float*)d_in[1];   // (1024, 1024)
    const float* W    = (const float*)d_in[2];   // (5, 1024, 1024)
    const float* bias = (const float*)d_in[3];   // (5, 1024)
    float* out = (float*)d_out;

    cudaFuncSetAttribute(gemm_mma_kernel,
                         cudaFuncAttributeMaxDynamicSharedMemorySize, SMEM_TOTAL);

    // Resource budget kept at the round-13-proven level: 3 streams, 6 events.
    static cudaStream_t st[NPIPE] = {};   // st[0] = default stream (nullptr)
    static cudaEvent_t evFork = nullptr, evPrep = nullptr;
    static cudaEvent_t evJoin[NPIPE] = {};
    if (!evFork) {
        cudaEventCreateWithFlags(&evFork, cudaEventDisableTiming);
        cudaEventCreateWithFlags(&evPrep, cudaEventDisableTiming);
        for (int q = 1; q < NPIPE; ++q) {
            cudaStreamCreateWithFlags(&st[q], cudaStreamNonBlocking);
            cudaEventCreateWithFlags(&evJoin[q], cudaEventDisableTiming);
        }
    }

    __half *bh, *bl, *ah;
    float *bufA;
    cudaGetSymbolAddress((void**)&bh,   g_Bh);
    cudaGetSymbolAddress((void**)&bl,   g_Bl);
    cudaGetSymbolAddress((void**)&ah,   g_A);
    cudaGetSymbolAddress((void**)&bufA, g_bufA);

    // layer-0 prep only before the fork (~3 us serial)
    prep_kernel<<<dim3(F_DIM / 32, F_DIM / 32, 1), dim3(32, 8)>>>(W, adj, 0);
    cudaEventRecord(evFork, 0);
    for (int q = 1; q < NPIPE; ++q) cudaStreamWaitEvent(st[q], evFork, 0);

    // layers 1-4 prep on EXISTING stream st[1], ahead of its pipeline;
    // overlaps with every pipeline's layer-0 GEMM.
    prep_kernel<<<dim3(F_DIM / 32, F_DIM / 32, L_LAYERS - 1), dim3(32, 8), 0, st[1]>>>(W, adj, 1);
    cudaEventRecord(evPrep, st[1]);

    const size_t p4 = (size_t)M_PIECE * F_DIM / 4;   // float4 units per piece
    const dim3 grid(F_DIM / BN, M_PIECE / BM);       // (8, 32)

    for (int q = 0; q < NPIPE; ++q) {
        cudaStream_t sq = st[q];   // q==0 -> default (nullptr)
        const size_t roff = (size_t)q * M_PIECE * F_DIM;
        tohalf_kernel<<<(int)(p4 / 256), 256, 0, sq>>>(x, (size_t)q * p4);
        for (int l = 0; l < L_LAYERS; ++l) {
            if (l == 1 && q != 1) cudaStreamWaitEvent(sq, evPrep, 0);  // st[1] ordered anyway
            const size_t bo = (size_t)l * F_DIM * F_DIM;
            const float* bias_l = bias + (size_t)l * F_DIM;
            const int last = (l == L_LAYERS - 1);
            gemm_mma_kernel<<<grid, THREADS, SMEM_TOTAL, sq>>>(
                ah + roff, bh + bo, bl + bo, bias_l, bufA + roff);
            ln_kernel<<<M_PIECE, 256, 0, sq>>>(bufA + roff,
                                               last ? (out + roff) : nullptr,
                                               ah + roff, last);
        }
    }

    // join side pipelines into default stream
    for (int q = 1; q < NPIPE; ++q) {
        cudaEventRecord(evJoin[q], st[q]);
        cudaStreamWaitEvent(0, evJoin[q], 0);
    }
}

// round 16
// speedup vs baseline: 1.0001x; 1.0001x over previous
#include <cuda_runtime.h>
#include <cuda_fp16.h>
#include <cstdint>

#define M_ROWS   16384
#define F_DIM    1024
#define L_LAYERS 5
#define NPIPE    4
#define M_QUART  (M_ROWS / NPIPE)   // 4096

#define BM 128
#define BN 128
#define BK 32
#define NCHUNK (F_DIM / BK)   // 32
#define THREADS 512
#define STAGES 4

#define ROW_BYTES   80
#define TILE_BYTES  (128 * ROW_BYTES)       // 10240
#define A_OFF       0u
#define BH_OFF      (1u * TILE_BYTES)
#define BL_OFF      (2u * TILE_BYTES)
#define STAGE_BYTES (3u * TILE_BYTES)       // 30720
#define SMEM_TOTAL  (STAGES * STAGE_BYTES)  // 122880

// ---------------- scratch ----------------
__device__ __half g_Bh[(size_t)L_LAYERS * F_DIM * F_DIM];  // 10 MB
__device__ __half g_Bl[(size_t)L_LAYERS * F_DIM * F_DIM];  // 10 MB
__device__ __half g_A [(size_t)M_ROWS * F_DIM];            // 32 MB  h (fp16): A AND residual
__device__ float g_bufA[(size_t)M_ROWS * F_DIM];           // 64 MB  ypre

// ---------------- helpers ----------------
__device__ __forceinline__ uint32_t smem_u32(const void* p) {
    uint32_t a;
    asm("{ .reg .u64 t; cvta.to.shared.u64 t, %1; cvt.u32.u64 %0, t; }" : "=r"(a) : "l"(p));
    return a;
}
__device__ __forceinline__ void cp_async16(uint32_t dst, const void* src) {
    asm volatile("cp.async.cg.shared.global [%0], [%1], 16;" :: "r"(dst), "l"(src));
}
#define CP_COMMIT()  asm volatile("cp.async.commit_group;")
#define CP_WAIT(n)   asm volatile("cp.async.wait_group %0;" :: "n"(n))

#define LDSM_X4(r, addr) \
    asm volatile("ldmatrix.sync.aligned.m8n8.x4.shared.b16 {%0,%1,%2,%3}, [%4];" \
        : "=r"((r)[0]), "=r"((r)[1]), "=r"((r)[2]), "=r"((r)[3]) : "r"(addr))

__device__ __forceinline__ void mma_f32acc(float* d, const uint32_t* a,
                                           uint32_t b0, uint32_t b1) {
    asm volatile(
        "mma.sync.aligned.m16n8k16.row.col.f32.f16.f16.f32 "
        "{%0,%1,%2,%3}, {%4,%5,%6,%7}, {%8,%9}, {%0,%1,%2,%3};"
        : "+f"(d[0]), "+f"(d[1]), "+f"(d[2]), "+f"(d[3])
        : "r"(a[0]), "r"(a[1]), "r"(a[2]), "r"(a[3]), "r"(b0), "r"(b1));
}
__device__ __forceinline__ void mma_f16acc(uint32_t* d, const uint32_t* a,
                                           uint32_t b0, uint32_t b1) {
    asm volatile(
        "mma.sync.aligned.m16n8k16.row.col.f16.f16.f16.f16 "
        "{%0,%1}, {%2,%3,%4,%5}, {%6,%7}, {%0,%1};"
        : "+r"(d[0]), "+r"(d[1])
        : "r"(a[0]), "r"(a[1]), "r"(a[2]), "r"(a[3]), "r"(b0), "r"(b1));
}

// ---------------- prep: B{h,l}[l][n][k] = split_fp16(W[l][k][n] * adj[k][n]) ----------------
__global__ void prep_kernel(const float* __restrict__ W, const float* __restrict__ adj) {
    __shared__ float tile[32][33];
    const int l = blockIdx.z;
    const int kb = blockIdx.x * 32;
    const int nb = blockIdx.y * 32;
    #pragma unroll
    for (int i = 0; i < 4; i++) {
        int k = kb + threadIdx.y + i * 8;
        int n = nb + threadIdx.x;
        tile[threadIdx.y + i * 8][threadIdx.x] =
            W[((size_t)l * F_DIM + k) * F_DIM + n] * adj[(size_t)k * F_DIM + n];
    }
    __syncthreads();
    #pragma unroll
    for (int i = 0; i < 4; i++) {
        int n = nb + threadIdx.y + i * 8;
        int k = kb + threadIdx.x;
        float v = tile[threadIdx.x][threadIdx.y + i * 8];
        __half h = __float2half(v);
        float rem = v - __half2float(h);
        size_t o = ((size_t)l * F_DIM + n) * F_DIM + k;
        g_Bh[o] = h;
        g_Bl[o] = __float2half(rem);
    }
}

// ---------------- x -> fp16 (per-quarter) ----------------
__global__ void tohalf_kernel(const float* __restrict__ X, size_t off4) {
    size_t idx = off4 + (size_t)blockIdx.x * blockDim.x + threadIdx.x;
    float4 v = ((const float4*)X)[idx];
    __half2 p0{__float2half(v.x), __float2half(v.y)};
    __half2 p1{__float2half(v.z), __float2half(v.w)};
    uint2 u;
    u.x = *(uint32_t*)&p0; u.y = *(uint32_t*)&p1;
    ((uint2*)g_A)[idx] = u;
}

// ---------------- GEMM: ypre = relu(A @ (Bh+Bl) + bias) + A   (A fp16; row-local) ----
__global__ void __launch_bounds__(THREADS, 1)
gemm_mma_kernel(const __half* __restrict__ A,
                const __half* __restrict__ Bh, const __half* __restrict__ Bl,
                const float* __restrict__ bias, float* __restrict__ Y)
{
    extern __shared__ char smem[];
    const uint32_t sb = smem_u32(smem);
    const int tid = threadIdx.x;
    const int wid = tid >> 5;
    const int lid = tid & 31;
    const int warpM = wid & 3;     // 4 warps in M, tile 32 rows
    const int warpN = wid >> 2;    // 4 warps in N, tile 32 cols
    const int blockRow = blockIdx.y * BM;
    const int blockCol = blockIdx.x * BN;

    const char* gA  = (const char*)(A  + (size_t)blockRow * F_DIM);
    const char* gBh = (const char*)(Bh + (size_t)blockCol * F_DIM);
    const char* gBl = (const char*)(Bl + (size_t)blockCol * F_DIM);

    auto load_stage = [&](int c, int s) {
        const int k0b = c * BK * 2;
        const uint32_t base = sb + (uint32_t)s * STAGE_BYTES;
        const int r = tid >> 2;
        const int c16 = tid & 3;
        const uint32_t soff = (uint32_t)(r * ROW_BYTES + c16 * 16);
        const size_t goff = (size_t)r * (F_DIM * 2) + k0b + c16 * 16;
        cp_async16(base + A_OFF  + soff, gA  + goff);
        cp_async16(base + BH_OFF + soff, gBh + goff);
        cp_async16(base + BL_OFF + soff, gBl + goff);
    };

    float    acc [2][4][4];
    uint32_t acch[2][4][2];
    #pragma unroll
    for (int mt = 0; mt < 2; mt++)
        #pragma unroll
        for (int nt = 0; nt < 4; nt++) {
            #pragma unroll
            for (int i = 0; i < 4; i++) acc[mt][nt][i] = 0.f;
            acch[mt][nt][0] = 0u; acch[mt][nt][1] = 0u;
        }

    load_stage(0, 0); CP_COMMIT();
    load_stage(1, 1); CP_COMMIT();
    load_stage(2, 2); CP_COMMIT();

    const uint32_t aRowOff = (uint32_t)((warpM * 32 + (lid & 15)) * ROW_BYTES + ((lid >> 4) << 4));
    const uint32_t bRowOff = (uint32_t)((warpN * 32 + (lid & 15)) * ROW_BYTES + ((lid >> 4) << 4));

    for (int c = 0; c < NCHUNK; ++c) {
        CP_WAIT(2);
        __syncthreads();
        if (c + 3 < NCHUNK) load_stage(c + 3, (c + 3) & 3);
        CP_COMMIT();

        const uint32_t stage = sb + (uint32_t)(c & 3) * STAGE_BYTES;
        #pragma unroll
        for (int kh = 0; kh < 2; kh++) {
            const uint32_t kb = (uint32_t)(kh * 32);
            uint32_t a[2][4], bh[2][4], bl[2][4];
            #pragma unroll
            for (int mt = 0; mt < 2; mt++)
                LDSM_X4(a[mt], stage + A_OFF + aRowOff + (uint32_t)(mt * 16 * ROW_BYTES) + kb);
            #pragma unroll
            for (int g = 0; g < 2; g++) {
                LDSM_X4(bh[g], stage + BH_OFF + bRowOff + (uint32_t)(g * 16 * ROW_BYTES) + kb);
                LDSM_X4(bl[g], stage + BL_OFF + bRowOff + (uint32_t)(g * 16 * ROW_BYTES) + kb);
            }
            #pragma unroll
            for (int mt = 0; mt < 2; mt++)
                #pragma unroll
                for (int nt = 0; nt < 4; nt++) {
                    const int g = nt >> 1, h = nt & 1;
                    mma_f32acc(acc[mt][nt], a[mt], bh[g][h], bh[g][h + 2]);
                }
            #pragma unroll
            for (int mt = 0; mt < 2; mt++)
                #pragma unroll
                for (int nt = 0; nt < 4; nt++) {
                    const int g = nt >> 1, h = nt & 1;
                    mma_f16acc(acch[mt][nt], a[mt], bl[g][h], bl[g][h + 2]);
                }
        }
    }

    // ---- epilogue: merge lo acc, bias + relu + residual (fp16 residual from A) ----
    const int lane4 = lid >> 2;
    const int lanec = (lid & 3) * 2;
    float2 bv[4];
    #pragma unroll
    for (int nt = 0; nt < 4; nt++)
        bv[nt] = *(const float2*)(bias + blockCol + warpN * 32 + nt * 8 + lanec);

    #pragma unroll
    for (int mt = 0; mt < 2; mt++) {
        const int r0 = blockRow + warpM * 32 + mt * 16 + lane4;
        const int r1 = r0 + 8;
        #pragma unroll
        for (int nt = 0; nt < 4; nt++) {
            const int col = blockCol + warpN * 32 + nt * 8 + lanec;
            const size_t o0 = (size_t)r0 * F_DIM + col;
            const size_t o1 = (size_t)r1 * F_DIM + col;
            float2 h0 = __half22float2(*(const __half2*)(A + o0));
            float2 h1 = __half22float2(*(const __half2*)(A + o1));
            float* a4 = acc[mt][nt];
            __half2 c0 = *(__half2*)&acch[mt][nt][0];
            __half2 c1 = *(__half2*)&acch[mt][nt][1];
            float s0 = a4[0] + __low2float(c0);
            float s1 = a4[1] + __high2float(c0);
            float s2 = a4[2] + __low2float(c1);
            float s3 = a4[3] + __high2float(c1);
            float2 y0, y1;
            y0.x = fmaxf(s0 + bv[nt].x, 0.f) + h0.x;
            y0.y = fmaxf(s1 + bv[nt].y, 0.f) + h0.y;
            y1.x = fmaxf(s2 + bv[nt].x, 0.f) + h1.x;
            y1.y = fmaxf(s3 + bv[nt].y, 0.f) + h1.y;
            *(float2*)(Y + o0) = y0;
            *(float2*)(Y + o1) = y1;
        }
    }
}

// ---------------- LayerNorm: pointer-parameterized ----------------
__global__ void ln_kernel(const float* __restrict__ Yin, float* __restrict__ OutF32,
                          __half* __restrict__ OutH, int last) {
    const int row = blockIdx.x;
    const size_t base4 = (size_t)row * (F_DIM / 4);
    float4 v = ((const float4*)Yin)[base4 + threadIdx.x];
    float s  = v.x + v.y + v.z + v.w;
    float ss = v.x * v.x + v.y * v.y + v.z * v.z + v.w * v.w;
    #pragma unroll
    for (int o = 16; o > 0; o >>= 1) {
        s  += __shfl_down_sync(0xffffffffu, s,  o);
        ss += __shfl_down_sync(0xffffffffu, ss, o);
    }
    __shared__ float sh_s[8], sh_ss[8];
    const int warp = threadIdx.x >> 5, lane = threadIdx.x & 31;
    if (lane == 0) { sh_s[warp] = s; sh_ss[warp] = ss; }
    __syncthreads();
    float st = 0.f, sst = 0.f;
    #pragma unroll
    for (int w = 0; w < 8; w++) { st += sh_s[w]; sst += sh_ss[w]; }
    const float inv = 1.0f / (float)F_DIM;
    const float mu  = st * inv;
    const float var = sst * inv - mu * mu;
    const float r   = rsqrtf(var + 1e-5f);
    v.x = (v.x - mu) * r; v.y = (v.y - mu) * r;
    v.z = (v.z - mu) * r; v.w = (v.w - mu) * r;
    if (last) {
        ((float4*)OutF32)[base4 + threadIdx.x] = v;
    } else {
        __half2 p0{__float2half(v.x), __float2half(v.y)};
        __half2 p1{__float2half(v.z), __float2half(v.w)};
        uint2 u;
        u.x = *(uint32_t*)&p0; u.y = *(uint32_t*)&p1;
        ((uint2*)OutH)[base4 + threadIdx.x] = u;
    }
}

// ---------------- launch: 4-way row-quarter pipelines across streams ----------------
extern "C" void kernel_launch(void* const* d_in, const int* in_sizes, int n_in,
                              void* d_out, int out_size) {
    const float* x    = (const float*)d_in[0];   // (16384, 1024)
    const float* adj  = (const float*)d_in[1];   // (1024, 1024)
    const float* W    = (const float*)d_in[2];   // (5, 1024, 1024)
    const float* bias = (const float*)d_in[3];   // (5, 1024)
    float* out = (float*)d_out;

    cudaFuncSetAttribute(gemm_mma_kernel,
                         cudaFuncAttributeMaxDynamicSharedMemorySize, SMEM_TOTAL);

    static cudaStream_t st[NPIPE] = {nullptr, nullptr, nullptr, nullptr};  // st[0] = default
    static cudaEvent_t evFork = nullptr;
    static cudaEvent_t evJoin[NPIPE] = {nullptr, nullptr, nullptr, nullptr};
    if (!evFork) {
        cudaEventCreateWithFlags(&evFork, cudaEventDisableTiming);
        for (int q = 1; q < NPIPE; ++q) {
            cudaStreamCreateWithFlags(&st[q], cudaStreamNonBlocking);
            cudaEventCreateWithFlags(&evJoin[q], cudaEventDisableTiming);
        }
    }

    __half *bh, *bl, *ah;
    float *bufA;
    cudaGetSymbolAddress((void**)&bh,   g_Bh);
    cudaGetSymbolAddress((void**)&bl,   g_Bl);
    cudaGetSymbolAddress((void**)&ah,   g_A);
    cudaGetSymbolAddress((void**)&bufA, g_bufA);

    // prep on default stream, then fork
    prep_kernel<<<dim3(F_DIM / 32, F_DIM / 32, L_LAYERS), dim3(32, 8)>>>(W, adj);
    cudaEventRecord(evFork, 0);
    for (int q = 1; q < NPIPE; ++q) cudaStreamWaitEvent(st[q], evFork, 0);

    const size_t q4 = (size_t)M_QUART * F_DIM / 4;   // float4 units per quarter
    const dim3 grid(F_DIM / BN, M_QUART / BM);       // (8, 32)

    for (int q = 0; q < NPIPE; ++q) {
        cudaStream_t sq = st[q];   // q==0 -> default (nullptr)
        const size_t roff = (size_t)q * M_QUART * F_DIM;
        tohalf_kernel<<<(int)(q4 / 256), 256, 0, sq>>>(x, (size_t)q * q4);
        for (int l = 0; l < L_LAYERS; ++l) {
            const size_t bo = (size_t)l * F_DIM * F_DIM;
            const float* bias_l = bias + (size_t)l * F_DIM;
            const int last = (l == L_LAYERS - 1);
            gemm_mma_kernel<<<grid, THREADS, SMEM_TOTAL, sq>>>(
                ah + roff, bh + bo, bl + bo, bias_l, bufA + roff);
            ln_kernel<<<M_QUART, 256, 0, sq>>>(bufA + roff,
                                               last ? (out + roff) : nullptr,
                                               ah + roff, last);
        }
    }

    // join side pipelines into default stream
    for (int q = 1; q < NPIPE; ++q) {
        cudaEventRecord(evJoin[q], st[q]);
        cudaStreamWaitEvent(0, evJoin[q], 0);
    }
}

// round 17
// speedup vs baseline: 1.0348x; 1.0346x over previous
#include <cuda_runtime.h>
#include <cuda_fp16.h>
#include <cstdint>

#define M_ROWS   16384
#define F_DIM    1024
#define L_LAYERS 5
#define NPIPE    4
#define M_QUART  (M_ROWS / NPIPE)   // 4096

#define BM 128
#define BN 128
#define BK 32
#define NCHUNK (F_DIM / BK)   // 32
#define THREADS 512
#define STAGES 4

#define ROW_BYTES   80
#define TILE_BYTES  (128 * ROW_BYTES)       // 10240
#define A_OFF       0u
#define BH_OFF      (1u * TILE_BYTES)
#define BL_OFF      (2u * TILE_BYTES)
#define STAGE_BYTES (3u * TILE_BYTES)       // 30720
#define SMEM_TOTAL  (STAGES * STAGE_BYTES)  // 122880

// ---------------- scratch ----------------
__device__ __half g_Bh[(size_t)L_LAYERS * F_DIM * F_DIM];  // 10 MB
__device__ __half g_Bl[(size_t)L_LAYERS * F_DIM * F_DIM];  // 10 MB
__device__ __half g_A [(size_t)M_ROWS * F_DIM];            // 32 MB  h (fp16): A AND residual
__device__ float g_bufA[(size_t)M_ROWS * F_DIM];           // 64 MB  ypre

// ---------------- helpers ----------------
__device__ __forceinline__ uint32_t smem_u32(const void* p) {
    uint32_t a;
    asm("{ .reg .u64 t; cvta.to.shared.u64 t, %1; cvt.u32.u64 %0, t; }" : "=r"(a) : "l"(p));
    return a;
}
__device__ __forceinline__ void cp_async16(uint32_t dst, const void* src) {
    asm volatile("cp.async.cg.shared.global [%0], [%1], 16;" :: "r"(dst), "l"(src));
}
#define CP_COMMIT()  asm volatile("cp.async.commit_group;")
#define CP_WAIT(n)   asm volatile("cp.async.wait_group %0;" :: "n"(n))

#define LDSM_X4(r, addr) \
    asm volatile("ldmatrix.sync.aligned.m8n8.x4.shared.b16 {%0,%1,%2,%3}, [%4];" \
        : "=r"((r)[0]), "=r"((r)[1]), "=r"((r)[2]), "=r"((r)[3]) : "r"(addr))

__device__ __forceinline__ void mma_f32acc(float* d, const uint32_t* a,
                                           uint32_t b0, uint32_t b1) {
    asm volatile(
        "mma.sync.aligned.m16n8k16.row.col.f32.f16.f16.f32 "
        "{%0,%1,%2,%3}, {%4,%5,%6,%7}, {%8,%9}, {%0,%1,%2,%3};"
        : "+f"(d[0]), "+f"(d[1]), "+f"(d[2]), "+f"(d[3])
        : "r"(a[0]), "r"(a[1]), "r"(a[2]), "r"(a[3]), "r"(b0), "r"(b1));
}
__device__ __forceinline__ void mma_f16acc(uint32_t* d, const uint32_t* a,
                                           uint32_t b0, uint32_t b1) {
    asm volatile(
        "mma.sync.aligned.m16n8k16.row.col.f16.f16.f16.f16 "
        "{%0,%1}, {%2,%3,%4,%5}, {%6,%7}, {%0,%1};"
        : "+r"(d[0]), "+r"(d[1])
        : "r"(a[0]), "r"(a[1]), "r"(a[2]), "r"(a[3]), "r"(b0), "r"(b1));
}

// ---------------- prep: B{h,l}[l][n][k] = split_fp16(W[l][k][n] * adj[k][n]) ----------------
__global__ void prep_kernel(const float* __restrict__ W, const float* __restrict__ adj) {
    __shared__ float tile[32][33];
    const int l = blockIdx.z;
    const int kb = blockIdx.x * 32;
    const int nb = blockIdx.y * 32;
    #pragma unroll
    for (int i = 0; i < 4; i++) {
        int k = kb + threadIdx.y + i * 8;
        int n = nb + threadIdx.x;
        tile[threadIdx.y + i * 8][threadIdx.x] =
            W[((size_t)l * F_DIM + k) * F_DIM + n] * adj[(size_t)k * F_DIM + n];
    }
    __syncthreads();
    #pragma unroll
    for (int i = 0; i < 4; i++) {
        int n = nb + threadIdx.y + i * 8;
        int k = kb + threadIdx.x;
        float v = tile[threadIdx.x][threadIdx.y + i * 8];
        __half h = __float2half(v);
        float rem = v - __half2float(h);
        size_t o = ((size_t)l * F_DIM + n) * F_DIM + k;
        g_Bh[o] = h;
        g_Bl[o] = __float2half(rem);
    }
}

// ---------------- x -> fp16 (per-quarter) ----------------
__global__ void tohalf_kernel(const float* __restrict__ X, size_t off4) {
    size_t idx = off4 + (size_t)blockIdx.x * blockDim.x + threadIdx.x;
    float4 v = ((const float4*)X)[idx];
    __half2 p0{__float2half(v.x), __float2half(v.y)};
    __half2 p1{__float2half(v.z), __float2half(v.w)};
    uint2 u;
    u.x = *(uint32_t*)&p0; u.y = *(uint32_t*)&p1;
    ((uint2*)g_A)[idx] = u;
}

// ---------------- GEMM: ypre = relu(A @ (Bh+Bl) + bias) + A   (A fp16; row-local) ----
__global__ void __launch_bounds__(THREADS, 1)
gemm_mma_kernel(const __half* __restrict__ A,
                const __half* __restrict__ Bh, const __half* __restrict__ Bl,
                const float* __restrict__ bias, float* __restrict__ Y)
{
    extern __shared__ char smem[];
    const uint32_t sb = smem_u32(smem);
    const int tid = threadIdx.x;
    const int wid = tid >> 5;
    const int lid = tid & 31;
    const int warpM = wid & 3;     // 4 warps in M, tile 32 rows
    const int warpN = wid >> 2;    // 4 warps in N, tile 32 cols
    const int blockRow = blockIdx.y * BM;
    const int blockCol = blockIdx.x * BN;

    const char* gA  = (const char*)(A  + (size_t)blockRow * F_DIM);
    const char* gBh = (const char*)(Bh + (size_t)blockCol * F_DIM);
    const char* gBl = (const char*)(Bl + (size_t)blockCol * F_DIM);

    auto load_stage = [&](int c, int s) {
        const int k0b = c * BK * 2;
        const uint32_t base = sb + (uint32_t)s * STAGE_BYTES;
        const int r = tid >> 2;
        const int c16 = tid & 3;
        const uint32_t soff = (uint32_t)(r * ROW_BYTES + c16 * 16);
        const size_t goff = (size_t)r * (F_DIM * 2) + k0b + c16 * 16;
        cp_async16(base + A_OFF  + soff, gA  + goff);
        cp_async16(base + BH_OFF + soff, gBh + goff);
        cp_async16(base + BL_OFF + soff, gBl + goff);
    };

    float    acc [2][4][4];
    uint32_t acch[2][4][2];
    #pragma unroll
    for (int mt = 0; mt < 2; mt++)
        #pragma unroll
        for (int nt = 0; nt < 4; nt++) {
            #pragma unroll
            for (int i = 0; i < 4; i++) acc[mt][nt][i] = 0.f;
            acch[mt][nt][0] = 0u; acch[mt][nt][1] = 0u;
        }

    load_stage(0, 0); CP_COMMIT();
    load_stage(1, 1); CP_COMMIT();
    load_stage(2, 2); CP_COMMIT();

    const uint32_t aRowOff = (uint32_t)((warpM * 32 + (lid & 15)) * ROW_BYTES + ((lid >> 4) << 4));
    const uint32_t bRowOff = (uint32_t)((warpN * 32 + (lid & 15)) * ROW_BYTES + ((lid >> 4) << 4));

    for (int c = 0; c < NCHUNK; ++c) {
        CP_WAIT(2);
        __syncthreads();
        if (c + 3 < NCHUNK) load_stage(c + 3, (c + 3) & 3);
        CP_COMMIT();

        const uint32_t stage = sb + (uint32_t)(c & 3) * STAGE_BYTES;
        #pragma unroll
        for (int kh = 0; kh < 2; kh++) {
            const uint32_t kb = (uint32_t)(kh * 32);
            uint32_t a[2][4], bh[2][4], bl[2][4];
            #pragma unroll
            for (int mt = 0; mt < 2; mt++)
                LDSM_X4(a[mt], stage + A_OFF + aRowOff + (uint32_t)(mt * 16 * ROW_BYTES) + kb);
            #pragma unroll
            for (int g = 0; g < 2; g++) {
                LDSM_X4(bh[g], stage + BH_OFF + bRowOff + (uint32_t)(g * 16 * ROW_BYTES) + kb);
                LDSM_X4(bl[g], stage + BL_OFF + bRowOff + (uint32_t)(g * 16 * ROW_BYTES) + kb);
            }
            #pragma unroll
            for (int mt = 0; mt < 2; mt++)
                #pragma unroll
                for (int nt = 0; nt < 4; nt++) {
                    const int g = nt >> 1, h = nt & 1;
                    mma_f32acc(acc[mt][nt], a[mt], bh[g][h], bh[g][h + 2]);
                }
            #pragma unroll
            for (int mt = 0; mt < 2; mt++)
                #pragma unroll
                for (int nt = 0; nt < 4; nt++) {
                    const int g = nt >> 1, h = nt & 1;
                    mma_f16acc(acch[mt][nt], a[mt], bl[g][h], bl[g][h + 2]);
                }
        }
    }

    // ---- epilogue: merge lo acc, bias + relu + residual (fp16 residual from A) ----
    const int lane4 = lid >> 2;
    const int lanec = (lid & 3) * 2;
    float2 bv[4];
    #pragma unroll
    for (int nt = 0; nt < 4; nt++)
        bv[nt] = *(const float2*)(bias + blockCol + warpN * 32 + nt * 8 + lanec);

    #pragma unroll
    for (int mt = 0; mt < 2; mt++) {
        const int r0 = blockRow + warpM * 32 + mt * 16 + lane4;
        const int r1 = r0 + 8;
        #pragma unroll
        for (int nt = 0; nt < 4; nt++) {
            const int col = blockCol + warpN * 32 + nt * 8 + lanec;
            const size_t o0 = (size_t)r0 * F_DIM + col;
            const size_t o1 = (size_t)r1 * F_DIM + col;
            float2 h0 = __half22float2(*(const __half2*)(A + o0));
            float2 h1 = __half22float2(*(const __half2*)(A + o1));
            float* a4 = acc[mt][nt];
            __half2 c0 = *(__half2*)&acch[mt][nt][0];
            __half2 c1 = *(__half2*)&acch[mt][nt][1];
            float s0 = a4[0] + __low2float(c0);
            float s1 = a4[1] + __high2float(c0);
            float s2 = a4[2] + __low2float(c1);
            float s3 = a4[3] + __high2float(c1);
            float2 y0, y1;
            y0.x = fmaxf(s0 + bv[nt].x, 0.f) + h0.x;
            y0.y = fmaxf(s1 + bv[nt].y, 0.f) + h0.y;
            y1.x = fmaxf(s2 + bv[nt].x, 0.f) + h1.x;
            y1.y = fmaxf(s3 + bv[nt].y, 0.f) + h1.y;
            *(float2*)(Y + o0) = y0;
            *(float2*)(Y + o1) = y1;
        }
    }
}

// ---------------- LayerNorm: warp-per-row, 8 rows/block, no barriers ----------------
__global__ void ln_kernel(const float* __restrict__ Yin, float* __restrict__ OutF32,
                          __half* __restrict__ OutH, int last) {
    const int warp = threadIdx.x >> 5;
    const int lane = threadIdx.x & 31;
    const int row  = blockIdx.x * 8 + warp;
    const size_t base4 = (size_t)row * (F_DIM / 4);

    // each lane loads 8 float4s (stride-32 across the row) -> MLP=8
    float4 v[8];
    #pragma unroll
    for (int i = 0; i < 8; i++)
        v[i] = ((const float4*)Yin)[base4 + lane + i * 32];

    float s = 0.f, ss = 0.f;
    #pragma unroll
    for (int i = 0; i < 8; i++) {
        s  += v[i].x + v[i].y + v[i].z + v[i].w;
        ss += v[i].x * v[i].x + v[i].y * v[i].y + v[i].z * v[i].z + v[i].w * v[i].w;
    }
    #pragma unroll
    for (int o = 16; o > 0; o >>= 1) {
        s  += __shfl_xor_sync(0xffffffffu, s,  o);
        ss += __shfl_xor_sync(0xffffffffu, ss, o);
    }
    const float inv = 1.0f / (float)F_DIM;
    const float mu  = s * inv;
    const float var = ss * inv - mu * mu;
    const float r   = rsqrtf(var + 1e-5f);

    if (last) {
        #pragma unroll
        for (int i = 0; i < 8; i++) {
            float4 o4;
            o4.x = (v[i].x - mu) * r; o4.y = (v[i].y - mu) * r;
            o4.z = (v[i].z - mu) * r; o4.w = (v[i].w - mu) * r;
            ((float4*)OutF32)[base4 + lane + i * 32] = o4;
        }
    } else {
        #pragma unroll
        for (int i = 0; i < 8; i++) {
            __half2 p0{__float2half((v[i].x - mu) * r), __float2half((v[i].y - mu) * r)};
            __half2 p1{__float2half((v[i].z - mu) * r), __float2half((v[i].w - mu) * r)};
            uint2 u;
            u.x = *(uint32_t*)&p0; u.y = *(uint32_t*)&p1;
            ((uint2*)OutH)[base4 + lane + i * 32] = u;
        }
    }
}

// ---------------- launch: 4-way row-quarter pipelines across streams ----------------
extern "C" void kernel_launch(void* const* d_in, const int* in_sizes, int n_in,
                              void* d_out, int out_size) {
    const float* x    = (const float*)d_in[0];   // (16384, 1024)
    const float* adj  = (const float*)d_in[1];   // (1024, 1024)
    const float* W    = (const float*)d_in[2];   // (5, 1024, 1024)
    const float* bias = (const float*)d_in[3];   // (5, 1024)
    float* out = (float*)d_out;

    cudaFuncSetAttribute(gemm_mma_kernel,
                         cudaFuncAttributeMaxDynamicSharedMemorySize, SMEM_TOTAL);

    static cudaStream_t st[NPIPE] = {nullptr, nullptr, nullptr, nullptr};  // st[0] = default
    static cudaEvent_t evFork = nullptr;
    static cudaEvent_t evJoin[NPIPE] = {nullptr, nullptr, nullptr, nullptr};
    if (!evFork) {
        cudaEventCreateWithFlags(&evFork, cudaEventDisableTiming);
        for (int q = 1; q < NPIPE; ++q) {
            cudaStreamCreateWithFlags(&st[q], cudaStreamNonBlocking);
            cudaEventCreateWithFlags(&evJoin[q], cudaEventDisableTiming);
        }
    }

    __half *bh, *bl, *ah;
    float *bufA;
    cudaGetSymbolAddress((void**)&bh,   g_Bh);
    cudaGetSymbolAddress((void**)&bl,   g_Bl);
    cudaGetSymbolAddress((void**)&ah,   g_A);
    cudaGetSymbolAddress((void**)&bufA, g_bufA);

    // prep on default stream, then fork
    prep_kernel<<<dim3(F_DIM / 32, F_DIM / 32, L_LAYERS), dim3(32, 8)>>>(W, adj);
    cudaEventRecord(evFork, 0);
    for (int q = 1; q < NPIPE; ++q) cudaStreamWaitEvent(st[q], evFork, 0);

    const size_t q4 = (size_t)M_QUART * F_DIM / 4;   // float4 units per quarter
    const dim3 grid(F_DIM / BN, M_QUART / BM);       // (8, 32)

    for (int q = 0; q < NPIPE; ++q) {
        cudaStream_t sq = st[q];   // q==0 -> default (nullptr)
        const size_t roff = (size_t)q * M_QUART * F_DIM;
        tohalf_kernel<<<(int)(q4 / 256), 256, 0, sq>>>(x, (size_t)q * q4);
        for (int l = 0; l < L_LAYERS; ++l) {
            const size_t bo = (size_t)l * F_DIM * F_DIM;
            const float* bias_l = bias + (size_t)l * F_DIM;
            const int last = (l == L_LAYERS - 1);
            gemm_mma_kernel<<<grid, THREADS, SMEM_TOTAL, sq>>>(
                ah + roff, bh + bo, bl + bo, bias_l, bufA + roff);
            ln_kernel<<<M_QUART / 8, 256, 0, sq>>>(bufA + roff,
                                                   last ? (out + roff) : nullptr,
                                                   ah + roff, last);
        }
    }

    // join side pipelines into default stream
    for (int q = 1; q < NPIPE; ++q) {
        cudaEventRecord(evJoin[q], st[q]);
        cudaStreamWaitEvent(0, evJoin[q], 0);
    }
}